// round 11
// baseline (speedup 1.0000x reference)
#include <cuda_runtime.h>
#include <cstdint>
#include <math_constants.h>

// B=64, I=1024, O=1024, et in {0,1,2}
// tnorm (op==0): val = (et==2 ? 1-x : x) + (et==0 ? +10 : 0), reduce = min
// tconorm:       same with -10, reduce = max
// Sign trick: s = tnorm ? +1 : -1.  w = s*v = (et==2 ? s - s*x : s*x) + (et==0 ? 10 : 0)
//   answer = s * min(w)   (exact; s*offset = +10 in both cases)

#define B_DIM 64
#define I_DIM 1024
#define O_DIM 1024
#define THREADS 64
#define WARPS_PB 2
#define ROWS_PER_BLOCK (WARPS_PB * 2)           // 4
#define GROUPS_PER_B (O_DIM / ROWS_PER_BLOCK)   // 256

static __device__ __forceinline__
float half_row_min(const int4* __restrict__ e, const float4* __restrict__ xs4,
                   int lane, float s)
{
    float red = CUDART_INF_F;
    #pragma unroll
    for (int j = 0; j < 4; ++j) {
        const float4 xv = xs4[j * 32 + lane];
        float t0 = s * xv.x, t1 = s * xv.y, t2 = s * xv.z, t3 = s * xv.w;
        float v0 = (e[j].x == 2) ? (s - t0) : t0;
        float v1 = (e[j].y == 2) ? (s - t1) : t1;
        float v2 = (e[j].z == 2) ? (s - t2) : t2;
        float v3 = (e[j].w == 2) ? (s - t3) : t3;
        if (e[j].x == 0) v0 += 10.0f;
        if (e[j].y == 0) v1 += 10.0f;
        if (e[j].z == 0) v2 += 10.0f;
        if (e[j].w == 0) v3 += 10.0f;
        red = fminf(red, fminf(fminf(v0, v1), fminf(v2, v3)));
    }
    return red;
}

static __device__ __forceinline__
float warp_min(float red)
{
    #pragma unroll
    for (int sh = 16; sh > 0; sh >>= 1)
        red = fminf(red, __shfl_xor_sync(0xffffffffu, red, sh));
    return red;
}

__global__ void __launch_bounds__(THREADS, 16)
ffcl_kernel(const float* __restrict__ x,
            const int4* __restrict__ et4,
            const int* __restrict__ op_idx,
            float* __restrict__ out)
{
    __shared__ float xs[I_DIM];                 // 4 KB

    const int b = blockIdx.x >> 8;              // / GROUPS_PER_B
    const int g = blockIdx.x & (GROUPS_PER_B - 1);

    const int warp = threadIdx.x >> 5;
    const int lane = threadIdx.x & 31;
    const int o0   = g * ROWS_PER_BLOCK + warp * 2;

    const int4* rowp = et4 + (size_t)(b * O_DIM + o0) * (I_DIM / 4);

    // ---- Prologue: 8 LDG.128 (row0 H0+H1) in flight BEFORE the barrier,
    //      so the (2-warp, near-free) barrier wait is covered by the et stream.
    int4 A[4], Bv[4];
    #pragma unroll
    for (int j = 0; j < 4; ++j)                  // H0: row0 first half
        A[j] = __ldcs(rowp + j * 32 + lane);
    #pragma unroll
    for (int j = 0; j < 4; ++j)                  // H1: row0 second half
        Bv[j] = __ldcs(rowp + 128 + j * 32 + lane);

    // Stage x[b,:] into shared: 4 float4 per thread (64 threads x 4 = 256).
    {
        const float4* xr = reinterpret_cast<const float4*>(x + (size_t)b * I_DIM);
        float4* xw = reinterpret_cast<float4*>(xs);
        xw[threadIdx.x]       = xr[threadIdx.x];
        xw[threadIdx.x + 64]  = xr[threadIdx.x + 64];
        xw[threadIdx.x + 128] = xr[threadIdx.x + 128];
        xw[threadIdx.x + 192] = xr[threadIdx.x + 192];
    }

    const float s0 = (op_idx[o0]     == 0) ? 1.0f : -1.0f;
    const float s1 = (op_idx[o0 + 1] == 0) ? 1.0f : -1.0f;

    __syncthreads();
    const float4* xs4 = reinterpret_cast<const float4*>(xs);

    // ---- Steady state: proven depth-1 rotation, barrier-free.
    float red0 = half_row_min(A, xs4, lane, s0);

    #pragma unroll
    for (int j = 0; j < 4; ++j)                  // H2: row1 first half
        A[j] = __ldcs(rowp + 256 + j * 32 + lane);

    red0 = fminf(red0, half_row_min(Bv, xs4 + 128, lane, s0));

    #pragma unroll
    for (int j = 0; j < 4; ++j)                  // H3: row1 second half
        Bv[j] = __ldcs(rowp + 384 + j * 32 + lane);

    red0 = warp_min(red0);
    if (lane == 0)
        out[(size_t)b * O_DIM + o0] = s0 * red0;

    float red1 = half_row_min(A, xs4, lane, s1);
    red1 = fminf(red1, half_row_min(Bv, xs4 + 128, lane, s1));
    red1 = warp_min(red1);
    if (lane == 0)
        out[(size_t)b * O_DIM + o0 + 1] = s1 * red1;
}

extern "C" void kernel_launch(void* const* d_in, const int* in_sizes, int n_in,
                              void* d_out, int out_size)
{
    (void)in_sizes; (void)n_in; (void)out_size;
    const float* x      = (const float*)d_in[0];
    const int4*  et4    = (const int4*)d_in[1];
    const int*   op_idx = (const int*)d_in[2];
    float*       out    = (float*)d_out;

    const int blocks = B_DIM * GROUPS_PER_B;    // 16384
    ffcl_kernel<<<blocks, THREADS>>>(x, et4, op_idx, out);
}

// round 12
// speedup vs baseline: 1.0062x; 1.0062x over previous
#include <cuda_runtime.h>
#include <cstdint>
#include <math_constants.h>

// B=64, I=1024, O=1024, et in {0,1,2}
// tnorm (op==0): val = (et==2 ? 1-x : x) + (et==0 ? +10 : 0), reduce = min
// tconorm:       same with -10, reduce = max
// Sign trick: s = tnorm ? +1 : -1.  w = s*v = (et==2 ? s - s*x : s*x) + (et==0 ? 10 : 0)
//   answer = s * min(w)   (exact; s*offset = +10 in both cases)

#define B_DIM 64
#define I_DIM 1024
#define O_DIM 1024
#define THREADS 128
#define WARPS_PB 4
#define ROWS_PER_BLOCK (WARPS_PB * 2)           // 8
#define GROUPS_PER_B (O_DIM / ROWS_PER_BLOCK)   // 128

static __device__ __forceinline__
float half_row_min(const int4* __restrict__ e, const float4* __restrict__ xs4,
                   int lane, float s)
{
    float red = CUDART_INF_F;
    #pragma unroll
    for (int j = 0; j < 4; ++j) {
        const float4 xv = xs4[j * 32 + lane];
        float t0 = s * xv.x, t1 = s * xv.y, t2 = s * xv.z, t3 = s * xv.w;
        float v0 = (e[j].x == 2) ? (s - t0) : t0;
        float v1 = (e[j].y == 2) ? (s - t1) : t1;
        float v2 = (e[j].z == 2) ? (s - t2) : t2;
        float v3 = (e[j].w == 2) ? (s - t3) : t3;
        if (e[j].x == 0) v0 += 10.0f;
        if (e[j].y == 0) v1 += 10.0f;
        if (e[j].z == 0) v2 += 10.0f;
        if (e[j].w == 0) v3 += 10.0f;
        red = fminf(red, fminf(fminf(v0, v1), fminf(v2, v3)));
    }
    return red;
}

static __device__ __forceinline__
float warp_min(float red)
{
    #pragma unroll
    for (int sh = 16; sh > 0; sh >>= 1)
        red = fminf(red, __shfl_xor_sync(0xffffffffu, red, sh));
    return red;
}

__global__ void __launch_bounds__(THREADS, 8)
ffcl_kernel(const float* __restrict__ x,
            const int4* __restrict__ et4,
            const int* __restrict__ op_idx,
            float* __restrict__ out)
{
    // Warp-private x stage (16 KB). Each lane writes ONLY the 8 float4 slots
    // it later reads (same thread) -> program-ordered, NO barriers anywhere.
    __shared__ __align__(16) float4 xs[WARPS_PB][I_DIM / 4];

    const int b = blockIdx.x >> 7;              // / GROUPS_PER_B
    const int g = blockIdx.x & (GROUPS_PER_B - 1);

    const int warp = threadIdx.x >> 5;
    const int lane = threadIdx.x & 31;
    const int o0   = g * ROWS_PER_BLOCK + warp * 2;

    const int4* rowp = et4 + (size_t)(b * O_DIM + o0) * (I_DIM / 4);

    // ---- Prologue: 8 LDG.128 (row0 H0+H1) issued first; the et stream
    //      covers the x-stage latency below.
    int4 A[4], Bv[4];
    #pragma unroll
    for (int j = 0; j < 4; ++j)                  // H0: row0 first half
        A[j] = __ldcs(rowp + j * 32 + lane);
    #pragma unroll
    for (int j = 0; j < 4; ++j)                  // H1: row0 second half
        Bv[j] = __ldcs(rowp + 128 + j * 32 + lane);

    // Stage this lane's 8 x-slots (x is L2-resident; overlaps et loads).
    {
        const float4* xr = reinterpret_cast<const float4*>(x + (size_t)b * I_DIM);
        float4* xw = xs[warp];
        #pragma unroll
        for (int j = 0; j < 8; ++j)
            xw[j * 32 + lane] = __ldg(xr + j * 32 + lane);
    }

    const float s0 = (op_idx[o0]     == 0) ? 1.0f : -1.0f;
    const float s1 = (op_idx[o0 + 1] == 0) ? 1.0f : -1.0f;

    const float4* xs4 = xs[warp];

    // ---- Steady state: proven depth-1 rotation, fully decoupled warps.
    float red0 = half_row_min(A, xs4, lane, s0);

    #pragma unroll
    for (int j = 0; j < 4; ++j)                  // H2: row1 first half
        A[j] = __ldcs(rowp + 256 + j * 32 + lane);

    red0 = fminf(red0, half_row_min(Bv, xs4 + 128, lane, s0));

    #pragma unroll
    for (int j = 0; j < 4; ++j)                  // H3: row1 second half
        Bv[j] = __ldcs(rowp + 384 + j * 32 + lane);

    red0 = warp_min(red0);
    if (lane == 0)
        out[(size_t)b * O_DIM + o0] = s0 * red0;

    float red1 = half_row_min(A, xs4, lane, s1);
    red1 = fminf(red1, half_row_min(Bv, xs4 + 128, lane, s1));
    red1 = warp_min(red1);
    if (lane == 0)
        out[(size_t)b * O_DIM + o0 + 1] = s1 * red1;
}

extern "C" void kernel_launch(void* const* d_in, const int* in_sizes, int n_in,
                              void* d_out, int out_size)
{
    (void)in_sizes; (void)n_in; (void)out_size;
    const float* x      = (const float*)d_in[0];
    const int4*  et4    = (const int4*)d_in[1];
    const int*   op_idx = (const int*)d_in[2];
    float*       out    = (float*)d_out;

    const int blocks = B_DIM * GROUPS_PER_B;    // 8192
    ffcl_kernel<<<blocks, THREADS>>>(x, et4, op_idx, out);
}